// round 7
// baseline (speedup 1.0000x reference)
#include <cuda_runtime.h>
#include <math.h>
#include <stdint.h>

// ---------------------------------------------------------------------------
// F = 8192 frames, chain:
//   X[2049,F] -> E1[1000,F] -> E[400,F] -> Gx[800,F] -> scan H[200,F]
//   Cat=[H;E][600,F] -> T1[800,F] -> T2[400,F] -> D[1000,F] -> out[2049,F]
// ---------------------------------------------------------------------------
#define FMAX 8192

__device__ __align__(16) float g_W1p[1000 * 2052];   // W1 padded to K=2052
__device__ float g_E1 [1000 * FMAX];
__device__ float g_Cat[ 600 * FMAX];
__device__ float g_Gx [ 800 * FMAX];
__device__ float g_T1 [ 800 * FMAX];
__device__ float g_T2 [ 400 * FMAX];
__device__ float g_D  [1000 * FMAX];
__device__ float g_bsum[800];

__device__ __forceinline__ float sigf(float x) { return 1.0f / (1.0f + expf(-x)); }
__device__ __forceinline__ float tanha(float x) {
    float y; asm("tanh.approx.f32 %0, %1;" : "=f"(y) : "f"(x)); return y;
}
__device__ __forceinline__ float siga(float x) {
    return 0.5f * tanha(0.5f * x) + 0.5f;
}

// packed f32x2 helpers
__device__ __forceinline__ void fma2(unsigned long long& acc,
                                     unsigned long long a, unsigned long long b) {
    asm("fma.rn.f32x2 %0, %1, %2, %0;" : "+l"(acc) : "l"(a), "l"(b));
}
__device__ __forceinline__ unsigned long long pack2(float x, float y) {
    unsigned long long v;
    asm("mov.b64 %0, {%1, %2};" : "=l"(v) : "f"(x), "f"(y));
    return v;
}
__device__ __forceinline__ void unpack2(float& lo, float& hi, unsigned long long v) {
    asm("mov.b64 {%0, %1}, %2;" : "=f"(lo), "=f"(hi) : "l"(v));
}
__device__ __forceinline__ uint32_t s2u(const void* p) {
    uint32_t a;
    asm("{ .reg .u64 t; cvta.to.shared.u64 t, %1; cvt.u32.u64 %0, t; }"
        : "=r"(a) : "l"(p));
    return a;
}

// ---------------------------------------------------------------------------
// GEMM v4: C[M,N] = act(A[M,K] @ B[K,N] + bias[M]); ACT 0=lrelu,1=none,
// 2=sigmoid()*X.  BM=BN=128, BK=32, 256 threads, 8x8 thread tile, f32x2
// accumulators.  STATIC smem (32KB), plain LDG register prefetch of tile
// t+1 issued before computing tile t (latency hidden by ~4000cyc compute).
// Two __syncthreads per 32-k tile (half of R5's per-k rate).
// Requirements: lda % 4 == 0 (W1 pre-padded to 2052), Ka % 4 == 0, N % 64 == 0.
// ---------------------------------------------------------------------------
template <int ACT>
__global__ __launch_bounds__(256) void gemm_kernel(
    const float* __restrict__ A, int lda, int Ka,
    const float* __restrict__ B,
    const float* __restrict__ bias, float* __restrict__ C,
    int M, int N, int K, const float* __restrict__ X)
{
    constexpr int BM = 128, BN = 128, BK = 32;
    __shared__ float As[BK][BM];   // transposed A tile, 16KB
    __shared__ float Bs[BK][BN];   // 16KB

    const int tid  = threadIdx.x;
    const int tx   = tid & 15;
    const int ty   = tid >> 4;
    const int row0 = ty << 3;
    const int col0 = tx << 3;
    const int m0   = blockIdx.y * BM;
    const int n0   = blockIdx.x * BN;

    const int am  = tid >> 1;            // A row within tile (0..127)
    const int ak0 = (tid & 1) << 4;      // A k half (0 or 16)
    const int bk  = tid >> 3;            // B k row (0..31)
    const int bn  = (tid & 7) << 4;      // B col chunk (16 floats)

    const int NT = (Ka + BK - 1) / BK;

    float4 aR[4], bR[4];

    auto loadA = [&](int t) {
        const int gm = m0 + am;
        const float* src = A + (size_t)gm * lda + t * BK + ak0;
#pragma unroll
        for (int i = 0; i < 4; i++) {
            int k = t * BK + ak0 + 4 * i;
            aR[i] = (gm < M && k < Ka)
                      ? *reinterpret_cast<const float4*>(src + 4 * i)
                      : make_float4(0.f, 0.f, 0.f, 0.f);
        }
    };
    auto loadB = [&](int t) {
        const int krow = t * BK + bk;
        const float* src = B + (size_t)krow * N + n0 + bn;
#pragma unroll
        for (int i = 0; i < 4; i++) {
            bR[i] = (krow < K)
                      ? *reinterpret_cast<const float4*>(src + 4 * i)
                      : make_float4(0.f, 0.f, 0.f, 0.f);
        }
    };
    auto storeAB = [&]() {
#pragma unroll
        for (int i = 0; i < 4; i++) {
            int k = ak0 + 4 * i;
            As[k + 0][am] = aR[i].x;
            As[k + 1][am] = aR[i].y;
            As[k + 2][am] = aR[i].z;
            As[k + 3][am] = aR[i].w;
        }
#pragma unroll
        for (int i = 0; i < 4; i++)
            *reinterpret_cast<float4*>(&Bs[bk][bn + 4 * i]) = bR[i];
    };

    unsigned long long acc[8][4];
#pragma unroll
    for (int i = 0; i < 8; i++)
#pragma unroll
        for (int j = 0; j < 4; j++) acc[i][j] = 0ULL;

    loadA(0);
    loadB(0);

    for (int t = 0; t < NT; t++) {
        storeAB();
        __syncthreads();
        if (t + 1 < NT) { loadA(t + 1); loadB(t + 1); }   // LDGs in flight

#pragma unroll 8
        for (int kk = 0; kk < BK; kk++) {
            float4 a0 = *reinterpret_cast<const float4*>(&As[kk][row0]);
            float4 a1 = *reinterpret_cast<const float4*>(&As[kk][row0 + 4]);
            const ulonglong2* bp =
                reinterpret_cast<const ulonglong2*>(&Bs[kk][col0]);
            ulonglong2 bv0 = bp[0], bv1 = bp[1];
            unsigned long long b2[4] = {bv0.x, bv0.y, bv1.x, bv1.y};
            float ar[8] = {a0.x, a0.y, a0.z, a0.w, a1.x, a1.y, a1.z, a1.w};
#pragma unroll
            for (int i = 0; i < 8; i++) {
                unsigned long long ap = pack2(ar[i], ar[i]);
#pragma unroll
                for (int j = 0; j < 4; j++) fma2(acc[i][j], ap, b2[j]);
            }
        }
        __syncthreads();   // before next storeAB overwrites tiles
    }

    // epilogue
#pragma unroll
    for (int i = 0; i < 8; i++) {
        int m = m0 + row0 + i;
        if (m >= M) continue;
        float bv = bias[m];
#pragma unroll
        for (int j = 0; j < 4; j++) {
            float lo, hi;
            unpack2(lo, hi, acc[i][j]);
            int n = n0 + col0 + 2 * j;
            size_t idx = (size_t)m * N + n;
            float v0 = lo + bv, v1 = hi + bv;
            if (ACT == 0) {
                v0 = (v0 >= 0.0f) ? v0 : 0.01f * v0;
                v1 = (v1 >= 0.0f) ? v1 : 0.01f * v1;
            } else if (ACT == 2) {
                v0 = sigf(v0) * X[idx];
                v1 = sigf(v1) * X[idx + 1];
            }
            *reinterpret_cast<float2*>(&C[idx]) = make_float2(v0, v1);
        }
    }
}

// ---------------------------------------------------------------------------
// small prep kernels
// ---------------------------------------------------------------------------
__global__ void bias_sum_kernel(const float* __restrict__ a,
                                const float* __restrict__ b,
                                float* __restrict__ out, int n)
{
    int i = blockIdx.x * blockDim.x + threadIdx.x;
    if (i < n) out[i] = a[i] + b[i];
}

__global__ void pad_w1_kernel(const float* __restrict__ W1,
                              float* __restrict__ Wp)
{
    int i = blockIdx.x * blockDim.x + threadIdx.x;
    if (i < 1000 * 2052) {
        int r = i / 2052, c = i - r * 2052;
        Wp[i] = (c < 2049) ? W1[r * 2049 + c] : 0.0f;
    }
}

// ---------------------------------------------------------------------------
// LSTM scan — VERBATIM the version measured at 8.30ms (round 5 bench).
// 8-CTA cluster, 128 threads, mbarrier ping-pong, full __syncthreads before
// the tid0 remote arrives (BAR.SYNC drains DSMEM STS).
// ---------------------------------------------------------------------------
__global__ void __cluster_dims__(8, 1, 1) __launch_bounds__(128, 1)
lstm_scan_kernel(const float* __restrict__ Whh, const float* __restrict__ Gx,
                 float* __restrict__ Hout, int F)
{
    __shared__ __align__(16) float hbuf[2][200];   // h, double buffered
    __shared__ float sgate[100];
    __shared__ __align__(8) unsigned long long bars[2];

    const int tid  = threadIdx.x;
    const int rank = blockIdx.x;
    const bool valid = tid < 100;
    const int g    = tid / 25;                  // gate index (i,f,g,o)
    const int j    = tid % 25;
    const int grow = 200 * g + 25 * rank + j;   // global gate row

    // ---- whole W_hh row in registers: 100 packed f32x2 ----
    unsigned long long w[100];
    if (valid) {
        const float4* src = reinterpret_cast<const float4*>(Whh + (size_t)grow * 200);
#pragma unroll
        for (int k = 0; k < 50; k++) {
            float4 v = src[k];
            w[2 * k]     = pack2(v.x, v.y);
            w[2 * k + 1] = pack2(v.z, v.w);
        }
    } else {
#pragma unroll
        for (int k = 0; k < 100; k++) w[k] = 0ULL;
    }

    // ---- init shared state ----
    for (int i = tid; i < 400; i += 128)
        hbuf[i / 200][i % 200] = 0.0f;
    if (tid == 0) {
        asm volatile("mbarrier.init.shared.b64 [%0], 8;"
                     :: "r"(s2u(&bars[0])) : "memory");
        asm volatile("mbarrier.init.shared.b64 [%0], 8;"
                     :: "r"(s2u(&bars[1])) : "memory");
    }
    __syncthreads();

    // peer base addresses (mapa preserves intra-CTA offsets)
    const uint32_t hb_local  = s2u(&hbuf[0][0]);
    const uint32_t bar_delta = s2u(&bars[0]) - hb_local;
    uint32_t peer_h[8];
#pragma unroll
    for (int r = 0; r < 8; r++)
        asm("mapa.shared::cluster.u32 %0, %1, %2;"
            : "=r"(peer_h[r]) : "r"(hb_local), "r"(r));

    // barriers + zeroed buffers visible cluster-wide before first step
    asm volatile("barrier.cluster.arrive.aligned;" ::: "memory");
    asm volatile("barrier.cluster.wait.aligned;"   ::: "memory");

    float c_state = 0.0f;                       // tid<25 owns c[25*rank+tid]
    float gx_cur = valid ? __ldg(&Gx[(size_t)grow * F]) : 0.0f;
    int ph[2] = {0, 0};

    for (int t = 0; t < F; t++) {
        const int pb = t & 1;
        float gx_next = (valid && (t + 1 < F))
                          ? __ldg(&Gx[(size_t)grow * F + t + 1]) : 0.0f;

        // ---- GEMV: full 200-col row, 4 interleaved f32x2 accumulators ----
        if (valid) {
            const ulonglong2* h4 =
                reinterpret_cast<const ulonglong2*>(&hbuf[pb][0]);
            unsigned long long a0 = 0ULL, a1 = 0ULL, a2 = 0ULL, a3 = 0ULL;
#pragma unroll
            for (int k = 0; k < 25; k++) {
                ulonglong2 hA = h4[2 * k];
                ulonglong2 hB = h4[2 * k + 1];
                fma2(a0, w[4 * k],     hA.x);
                fma2(a1, w[4 * k + 1], hA.y);
                fma2(a2, w[4 * k + 2], hB.x);
                fma2(a3, w[4 * k + 3], hB.y);
            }
            float l0, h0, l1, h1, l2, h2, l3, h3;
            unpack2(l0, h0, a0); unpack2(l1, h1, a1);
            unpack2(l2, h2, a2); unpack2(l3, h3, a3);
            sgate[tid] = ((l0 + h0) + (l1 + h1)) + ((l2 + h2) + (l3 + h3))
                         + gx_cur;
        }
        gx_cur = gx_next;
        __syncthreads();

        // ---- LSTM update + push h slice to every CTA's next-buffer ----
        if (tid < 25) {
            float gi = sgate[tid];
            float gf = sgate[25 + tid];
            float gg = sgate[50 + tid];
            float go = sgate[75 + tid];
            float cn = siga(gf) * c_state + siga(gi) * tanha(gg);
            float hn = siga(go) * tanha(cn);
            c_state = cn;
            Hout[(size_t)(25 * rank + tid) * F + t] = hn;
            uint32_t off = (uint32_t)((((t + 1) & 1) * 200 + 25 * rank + tid) * 4);
#pragma unroll
            for (int r = 0; r < 8; r++)
                asm volatile("st.shared::cluster.f32 [%0], %1;"
                             :: "r"(peer_h[r] + off), "f"(hn) : "memory");
        }

        // BAR.SYNC drains pending STS (incl. DSMEM) before the signal
        __syncthreads();

        // ---- signal: one arrive per peer barrier (count 8) ----
        if (tid == 0) {
#pragma unroll
            for (int r = 0; r < 8; r++) {
                uint32_t ba = peer_h[r] + bar_delta + (uint32_t)(pb * 8);
                asm volatile("mbarrier.arrive.shared::cluster.b64 _, [%0];"
                             :: "r"(ba) : "memory");
            }
        }

        // ---- wait: local bars[pb], parity ph[pb] ----
        {
            const uint32_t ba = s2u(&bars[pb]);
            uint32_t done;
            asm volatile(
                "{\n\t.reg .pred p;\n\t"
                "mbarrier.try_wait.parity.acquire.cta.shared::cta.b64 p, [%1], %2;\n\t"
                "selp.b32 %0, 1, 0, p;\n\t}"
                : "=r"(done) : "r"(ba), "r"((uint32_t)ph[pb]) : "memory");
            if (!done) {
                asm volatile(
                    "{\n\t.reg .pred P1;\n\t"
                    "WL_%=:\n\t"
                    "mbarrier.try_wait.parity.acquire.cta.shared::cta.b64 P1, [%0], %1, 0x989680;\n\t"
                    "@P1 bra.uni WD_%=;\n\t"
                    "bra.uni WL_%=;\n\t"
                    "WD_%=:\n\t}"
                    :: "r"(ba), "r"((uint32_t)ph[pb]) : "memory");
            }
            ph[pb] ^= 1;
        }
    }

    // keep SMEM alive until every CTA's final stores/arrives landed
    asm volatile("barrier.cluster.arrive.aligned;" ::: "memory");
    asm volatile("barrier.cluster.wait.aligned;"   ::: "memory");
}

// ---------------------------------------------------------------------------
// launch
// ---------------------------------------------------------------------------
extern "C" void kernel_launch(void* const* d_in, const int* in_sizes, int n_in,
                              void* d_out, int out_size)
{
    const float* mag = (const float*)d_in[0];
    const float* W1  = (const float*)d_in[1];
    const float* b1  = (const float*)d_in[2];
    const float* W2  = (const float*)d_in[3];
    const float* b2  = (const float*)d_in[4];
    const float* W3  = (const float*)d_in[5];
    const float* b3  = (const float*)d_in[6];
    const float* W4  = (const float*)d_in[7];
    const float* b4  = (const float*)d_in[8];
    const float* Wf1 = (const float*)d_in[9];
    const float* bf1 = (const float*)d_in[10];
    const float* Wf2 = (const float*)d_in[11];
    const float* bf2 = (const float*)d_in[12];
    const float* Wih = (const float*)d_in[13];
    const float* bih = (const float*)d_in[14];
    const float* Whh = (const float*)d_in[15];
    const float* bhh = (const float*)d_in[16];

    const int F = in_sizes[0] / 2049;
    float* out = (float*)d_out;

    float *W1p, *E1, *Cat, *Gxp, *T1, *T2, *D, *bsum;
    cudaGetSymbolAddress((void**)&W1p,  g_W1p);
    cudaGetSymbolAddress((void**)&E1,   g_E1);
    cudaGetSymbolAddress((void**)&Cat,  g_Cat);
    cudaGetSymbolAddress((void**)&Gxp,  g_Gx);
    cudaGetSymbolAddress((void**)&T1,   g_T1);
    cudaGetSymbolAddress((void**)&T2,   g_T2);
    cudaGetSymbolAddress((void**)&D,    g_D);
    cudaGetSymbolAddress((void**)&bsum, g_bsum);

    float* E = Cat + (size_t)200 * F;   // E lives inside Cat rows 200..600

    dim3 blk(256);
    auto grid = [&](int M) { return dim3(F / 128, (M + 127) / 128); };

    bias_sum_kernel<<<4, 256>>>(bih, bhh, bsum, 800);
    pad_w1_kernel<<<(1000 * 2052 + 255) / 256, 256>>>(W1, W1p);

    // phase 1 (batched)
    gemm_kernel<0><<<grid(1000), blk>>>(W1p, 2052, 2052, mag, b1, E1,
                                        1000, F, 2049, nullptr);
    gemm_kernel<0><<<grid(400),  blk>>>(W2, 1000, 1000, E1, b2, E,
                                        400, F, 1000, nullptr);
    gemm_kernel<1><<<grid(800),  blk>>>(Wih, 400, 400, E, bsum, Gxp,
                                        800, F, 400, nullptr);

    // sequential LSTM scan -> Cat rows 0..200
    lstm_scan_kernel<<<8, 128>>>(Whh, Gxp, Cat, F);

    // phase 2 (batched)
    gemm_kernel<0><<<grid(800),  blk>>>(Wf1, 600, 600, Cat, bf1, T1,
                                        800, F, 600, nullptr);
    gemm_kernel<0><<<grid(400),  blk>>>(Wf2, 800, 800, T1, bf2, T2,
                                        400, F, 800, nullptr);
    gemm_kernel<0><<<grid(1000), blk>>>(W3, 400, 400, T2, b3, D,
                                        1000, F, 400, nullptr);
    gemm_kernel<2><<<grid(2049), blk>>>(W4, 1000, 1000, D, b4, out,
                                        2049, F, 1000, mag);
}

// round 9
// speedup vs baseline: 1.2820x; 1.2820x over previous
#include <cuda_runtime.h>
#include <cuda_bf16.h>
#include <math.h>
#include <stdint.h>

typedef __nv_bfloat16 bf16;

// ---------------------------------------------------------------------------
// Frame-major dataflow, F = 8192:
//  magT(Xh/Xl)[F,2112] -> E1[F,1024] -> Cat[F,712] (H 0..200 | E 200..712)
//  -> Gx[F,896] f32 -> scan -> Cat H -> T1[F,896] -> T2[F,512] -> D[F,1024]
//  -> out[2049,F]
// All activations/weights stored as bf16 hi/lo pairs (hi+lo ~ fp32@2^-17).
// Weight pads (rows>=M, cols>=K) are ZERO -> they kill A-side pad garbage.
// GEMMs run on tensor cores via mma.sync (HMMA; tcgen05 not available at
// compute_100 PTX target per round-8 ptxas errors).
// ---------------------------------------------------------------------------
#define FF 8192

__device__ __align__(16) bf16 g_Xh [FF * 2112], g_Xl [FF * 2112];
__device__ __align__(16) bf16 g_W1h[1024 * 2112], g_W1l[1024 * 2112];
__device__ __align__(16) bf16 g_W2h[ 512 * 1024], g_W2l[ 512 * 1024];
__device__ __align__(16) bf16 g_Wih_h[896 * 512], g_Wih_l[896 * 512];
__device__ __align__(16) bf16 g_Wf1h[896 * 640],  g_Wf1l[896 * 640];
__device__ __align__(16) bf16 g_Wf2h[512 * 896],  g_Wf2l[512 * 896];
__device__ __align__(16) bf16 g_W3h[1024 * 512],  g_W3l[1024 * 512];
__device__ __align__(16) bf16 g_W4h[2176 * 1024], g_W4l[2176 * 1024];
__device__ __align__(16) bf16 g_E1h[FF * 1024],   g_E1l[FF * 1024];
__device__ __align__(16) bf16 g_Cath[FF * 712],   g_Catl[FF * 712];
__device__ __align__(16) float g_Gx [FF * 896];
__device__ __align__(16) bf16 g_T1h[FF * 896],    g_T1l[FF * 896];
__device__ __align__(16) bf16 g_T2h[FF * 512],    g_T2l[FF * 512];
__device__ __align__(16) bf16 g_Dh [FF * 1024],   g_Dl [FF * 1024];
__device__ float g_bsum[800];

__device__ __forceinline__ float sigf(float x) { return 1.0f / (1.0f + expf(-x)); }
__device__ __forceinline__ float tanha(float x) {
    float y; asm("tanh.approx.f32 %0, %1;" : "=f"(y) : "f"(x)); return y;
}
__device__ __forceinline__ float siga(float x) {
    return 0.5f * tanha(0.5f * x) + 0.5f;
}
__device__ __forceinline__ uint32_t s2u(const void* p) {
    uint32_t a;
    asm("{ .reg .u64 t; cvta.to.shared.u64 t, %1; cvt.u32.u64 %0, t; }"
        : "=r"(a) : "l"(p));
    return a;
}
__device__ __forceinline__ void mbar_wait(uint32_t ba, uint32_t par) {
    uint32_t done;
    asm volatile(
        "{\n\t.reg .pred p;\n\t"
        "mbarrier.try_wait.parity.acquire.cta.shared::cta.b64 p, [%1], %2;\n\t"
        "selp.b32 %0, 1, 0, p;\n\t}"
        : "=r"(done) : "r"(ba), "r"(par) : "memory");
    if (!done) {
        asm volatile(
            "{\n\t.reg .pred P1;\n\t"
            "WL_%=:\n\t"
            "mbarrier.try_wait.parity.acquire.cta.shared::cta.b64 P1, [%0], %1, 0x989680;\n\t"
            "@P1 bra.uni WD_%=;\n\t"
            "bra.uni WL_%=;\n\t"
            "WD_%=:\n\t}"
            :: "r"(ba), "r"(par) : "memory");
    }
}
// packed f32x2 (scan)
__device__ __forceinline__ void fma2(unsigned long long& acc,
                                     unsigned long long a, unsigned long long b) {
    asm("fma.rn.f32x2 %0, %1, %2, %0;" : "+l"(acc) : "l"(a), "l"(b));
}
__device__ __forceinline__ unsigned long long pack2(float x, float y) {
    unsigned long long v;
    asm("mov.b64 %0, {%1, %2};" : "=l"(v) : "f"(x), "f"(y));
    return v;
}
__device__ __forceinline__ void unpack2(float& lo, float& hi, unsigned long long v) {
    asm("mov.b64 {%0, %1}, %2;" : "=f"(lo), "=f"(hi) : "l"(v));
}

// mma.sync m16n8k16 bf16 (row.col), f32 accum
__device__ __forceinline__ void mma16816(float d[4],
                                         uint32_t a0, uint32_t a1,
                                         uint32_t a2, uint32_t a3,
                                         uint32_t b0, uint32_t b1) {
    asm volatile(
        "mma.sync.aligned.m16n8k16.row.col.f32.bf16.bf16.f32 "
        "{%0,%1,%2,%3}, {%4,%5,%6,%7}, {%8,%9}, {%0,%1,%2,%3};"
        : "+f"(d[0]), "+f"(d[1]), "+f"(d[2]), "+f"(d[3])
        : "r"(a0), "r"(a1), "r"(a2), "r"(a3), "r"(b0), "r"(b1));
}

// ---------------------------------------------------------------------------
// mma_gemm<ACT>: D[128f x 128c] per CTA, 256 threads (8 warps, each 64x32 =
// 4 m16 x 4 n8).  A = act[F,lda] bf16 hi/lo (k contiguous), B = W[Mp,Kpad]
// bf16 hi/lo (k contiguous).  K processed in 64-chunks, single-buffer smem,
// pitch 72 bf16 (fragment LDS bank-free: bank = 4g+tg covers 0..31).
// Split precision: 3 MMAs per tile (AhBh + AlBh + AhBl).
// ACT 0: lrelu -> bf16 pair at Chi/Clo[f*ldc + cofs + c]
// ACT 1: +bias -> f32 Cf[f*ldc + c]
// ACT 2: sigmoid(v)*mag[c*F+f] -> outp[c*F+f], guard c<2049
// ---------------------------------------------------------------------------
template <int ACT>
__global__ void __launch_bounds__(256) mma_gemm(
    const bf16* __restrict__ Ah, const bf16* __restrict__ Al, int lda,
    const bf16* __restrict__ Wh, const bf16* __restrict__ Wl, int Kpad,
    const float* __restrict__ bias, int M,
    bf16* __restrict__ Chi, bf16* __restrict__ Clo, float* __restrict__ Cf,
    int ldc, int cofs,
    const float* __restrict__ mag, float* __restrict__ outp, int F)
{
    constexpr int P  = 72;   // smem pitch (bf16)
    constexpr int PW = 36;   // smem pitch (32-bit words)
    extern __shared__ bf16 smg[];
    bf16* sAh = smg;
    bf16* sAl = sAh + 128 * P;
    bf16* sWh = sAl + 128 * P;
    bf16* sWl = sWh + 128 * P;        // total 73728 B

    const int tid  = threadIdx.x;
    const int w    = tid >> 5;
    const int lane = tid & 31;
    const int g    = lane >> 2;       // group 0..7
    const int tg   = lane & 3;        // thread-in-group
    const int wm   = (w & 1) * 64;    // warp frame offset
    const int wn   = (w >> 1) * 32;   // warp channel offset
    const int f0   = blockIdx.x * 128;
    const int m0   = blockIdx.y * 128;
    const int lrow = tid >> 1;        // load row 0..127
    const int lcol = (tid & 1) * 32;  // load col half

    const uint32_t* s32Ah = reinterpret_cast<const uint32_t*>(sAh);
    const uint32_t* s32Al = reinterpret_cast<const uint32_t*>(sAl);
    const uint32_t* s32Wh = reinterpret_cast<const uint32_t*>(sWh);
    const uint32_t* s32Wl = reinterpret_cast<const uint32_t*>(sWl);

    float acc[4][4][4];
#pragma unroll
    for (int mt = 0; mt < 4; mt++)
#pragma unroll
        for (int nt = 0; nt < 4; nt++)
#pragma unroll
            for (int q = 0; q < 4; q++) acc[mt][nt][q] = 0.0f;

    const int NC = Kpad >> 6;
    for (int ci = 0; ci < NC; ci++) {
        const int k0 = ci << 6;
        // gmem loads (4 uint4 per tile per thread)
        uint4 rA[4], rB[4], rC[4], rD[4];
        {
            const uint4* pA = reinterpret_cast<const uint4*>(
                Ah + (size_t)(f0 + lrow) * lda + k0 + lcol);
            const uint4* pB = reinterpret_cast<const uint4*>(
                Al + (size_t)(f0 + lrow) * lda + k0 + lcol);
            const uint4* pC = reinterpret_cast<const uint4*>(
                Wh + (size_t)(m0 + lrow) * Kpad + k0 + lcol);
            const uint4* pD = reinterpret_cast<const uint4*>(
                Wl + (size_t)(m0 + lrow) * Kpad + k0 + lcol);
#pragma unroll
            for (int i = 0; i < 4; i++) {
                rA[i] = pA[i]; rB[i] = pB[i]; rC[i] = pC[i]; rD[i] = pD[i];
            }
        }
        __syncthreads();              // previous chunk's compute done
        {
            uint4* dA = reinterpret_cast<uint4*>(sAh + lrow * P + lcol);
            uint4* dB = reinterpret_cast<uint4*>(sAl + lrow * P + lcol);
            uint4* dC = reinterpret_cast<uint4*>(sWh + lrow * P + lcol);
            uint4* dD = reinterpret_cast<uint4*>(sWl + lrow * P + lcol);
#pragma unroll
            for (int i = 0; i < 4; i++) {
                dA[i] = rA[i]; dB[i] = rB[i]; dC[i] = rC[i]; dD[i] = rD[i];
            }
        }
        __syncthreads();

        // compute: 4 k16 steps
#pragma unroll
        for (int kk = 0; kk < 4; kk++) {
            uint32_t bh[4][2], bl[4][2];
#pragma unroll
            for (int nt = 0; nt < 4; nt++) {
                int br = (wn + nt * 8 + g) * PW + kk * 8 + tg;
                bh[nt][0] = s32Wh[br];      bh[nt][1] = s32Wh[br + 4];
                bl[nt][0] = s32Wl[br];      bl[nt][1] = s32Wl[br + 4];
            }
#pragma unroll
            for (int mt = 0; mt < 4; mt++) {
                int ar = (wm + mt * 16 + g) * PW + kk * 8 + tg;
                uint32_t ah0 = s32Ah[ar];
                uint32_t ah1 = s32Ah[ar + 8 * PW];
                uint32_t ah2 = s32Ah[ar + 4];
                uint32_t ah3 = s32Ah[ar + 8 * PW + 4];
                uint32_t al0 = s32Al[ar];
                uint32_t al1 = s32Al[ar + 8 * PW];
                uint32_t al2 = s32Al[ar + 4];
                uint32_t al3 = s32Al[ar + 8 * PW + 4];
#pragma unroll
                for (int nt = 0; nt < 4; nt++) {
                    mma16816(acc[mt][nt], ah0, ah1, ah2, ah3, bh[nt][0], bh[nt][1]);
                    mma16816(acc[mt][nt], al0, al1, al2, al3, bh[nt][0], bh[nt][1]);
                    mma16816(acc[mt][nt], ah0, ah1, ah2, ah3, bl[nt][0], bl[nt][1]);
                }
            }
        }
    }

    // ---- epilogue ----
#pragma unroll
    for (int mt = 0; mt < 4; mt++) {
        const int fa = f0 + wm + mt * 16 + g;
#pragma unroll
        for (int nt = 0; nt < 4; nt++) {
            const int c0 = m0 + wn + nt * 8 + 2 * tg;
            const float bv0 = (c0 < M)     ? __ldg(&bias[c0])     : 0.0f;
            const float bv1 = (c0 + 1 < M) ? __ldg(&bias[c0 + 1]) : 0.0f;
#pragma unroll
            for (int hrow = 0; hrow < 2; hrow++) {
                const int f = fa + hrow * 8;
                float v0 = acc[mt][nt][2 * hrow]     + bv0;
                float v1 = acc[mt][nt][2 * hrow + 1] + bv1;
                if (ACT == 0) {
                    v0 = (v0 >= 0.0f) ? v0 : 0.01f * v0;
                    v1 = (v1 >= 0.0f) ? v1 : 0.01f * v1;
                    bf16 h0 = __float2bfloat16(v0);
                    bf16 h1 = __float2bfloat16(v1);
                    bf16 l0 = __float2bfloat16(v0 - __bfloat162float(h0));
                    bf16 l1 = __float2bfloat16(v1 - __bfloat162float(h1));
                    uint32_t hw = ((uint32_t)__bfloat16_as_ushort(h1) << 16)
                                  | __bfloat16_as_ushort(h0);
                    uint32_t lw = ((uint32_t)__bfloat16_as_ushort(l1) << 16)
                                  | __bfloat16_as_ushort(l0);
                    size_t off = (size_t)f * ldc + cofs + c0;
                    *reinterpret_cast<uint32_t*>(Chi + off) = hw;
                    *reinterpret_cast<uint32_t*>(Clo + off) = lw;
                } else if (ACT == 1) {
                    *reinterpret_cast<float2*>(Cf + (size_t)f * ldc + c0) =
                        make_float2(v0, v1);
                } else {
                    if (c0 < 2049) {
                        size_t idx = (size_t)c0 * F + f;
                        outp[idx] = sigf(v0) * __ldg(&mag[idx]);
                    }
                    if (c0 + 1 < 2049) {
                        size_t idx = (size_t)(c0 + 1) * F + f;
                        outp[idx] = sigf(v1) * __ldg(&mag[idx]);
                    }
                }
            }
        }
    }
}

// ---------------------------------------------------------------------------
// prep kernels
// ---------------------------------------------------------------------------
__global__ void bias_sum_kernel(const float* __restrict__ a,
                                const float* __restrict__ b,
                                float* __restrict__ out, int n)
{
    int i = blockIdx.x * blockDim.x + threadIdx.x;
    if (i < n) out[i] = a[i] + b[i];
}

__global__ void split_weight(const float* __restrict__ W, int M, int K,
                             bf16* __restrict__ Wh, bf16* __restrict__ Wl,
                             int Mp, int Kp)
{
    int i = blockIdx.x * blockDim.x + threadIdx.x;
    if (i >= Mp * Kp) return;
    int r = i / Kp, c = i - r * Kp;
    float v = (r < M && c < K) ? W[(size_t)r * K + c] : 0.0f;
    bf16 h = __float2bfloat16(v);
    Wh[i] = h;
    Wl[i] = __float2bfloat16(v - __bfloat162float(h));
}

// mag[2049,F] -> Xh/Xl [F,2112] (transposed, split, zero-padded)
__global__ void transpose_split_mag(const float* __restrict__ mag,
                                    bf16* __restrict__ Xh, bf16* __restrict__ Xl,
                                    int F)
{
    __shared__ float sm[32][33];
    const int ft = blockIdx.x * 32, ct = blockIdx.y * 32;
    const int tx = threadIdx.x, ty = threadIdx.y;
#pragma unroll
    for (int i = 0; i < 4; i++) {
        int c = ct + ty + i * 8;
        sm[ty + i * 8][tx] = (c < 2049) ? mag[(size_t)c * F + ft + tx] : 0.0f;
    }
    __syncthreads();
#pragma unroll
    for (int i = 0; i < 4; i++) {
        int f = ft + ty + i * 8;
        int c = ct + tx;
        float v = sm[tx][ty + i * 8];
        bf16 h = __float2bfloat16(v);
        size_t idx = (size_t)f * 2112 + c;
        Xh[idx] = h;
        Xl[idx] = __float2bfloat16(v - __bfloat162float(h));
    }
}

// ---------------------------------------------------------------------------
// LSTM scan — R5-proven structure; frame-major Gx read, H written as bf16
// hi/lo pair into Cat cols 0..200.
// ---------------------------------------------------------------------------
__global__ void __cluster_dims__(8, 1, 1) __launch_bounds__(128, 1)
lstm_scan_kernel(const float* __restrict__ Whh, const float* __restrict__ Gx,
                 bf16* __restrict__ CatH, bf16* __restrict__ CatL, int F)
{
    __shared__ __align__(16) float hbuf[2][200];
    __shared__ float sgate[100];
    __shared__ __align__(8) unsigned long long bars[2];

    const int tid  = threadIdx.x;
    const int rank = blockIdx.x;
    const bool valid = tid < 100;
    const int g    = tid / 25;
    const int j    = tid % 25;
    const int grow = 200 * g + 25 * rank + j;

    unsigned long long w[100];
    if (valid) {
        const float4* src = reinterpret_cast<const float4*>(Whh + (size_t)grow * 200);
#pragma unroll
        for (int k = 0; k < 50; k++) {
            float4 v = src[k];
            w[2 * k]     = pack2(v.x, v.y);
            w[2 * k + 1] = pack2(v.z, v.w);
        }
    } else {
#pragma unroll
        for (int k = 0; k < 100; k++) w[k] = 0ULL;
    }

    for (int i = tid; i < 400; i += 128)
        hbuf[i / 200][i % 200] = 0.0f;
    if (tid == 0) {
        asm volatile("mbarrier.init.shared.b64 [%0], 8;"
                     :: "r"(s2u(&bars[0])) : "memory");
        asm volatile("mbarrier.init.shared.b64 [%0], 8;"
                     :: "r"(s2u(&bars[1])) : "memory");
    }
    __syncthreads();

    const uint32_t hb_local  = s2u(&hbuf[0][0]);
    const uint32_t bar_delta = s2u(&bars[0]) - hb_local;
    uint32_t peer_h[8];
#pragma unroll
    for (int r = 0; r < 8; r++)
        asm("mapa.shared::cluster.u32 %0, %1, %2;"
            : "=r"(peer_h[r]) : "r"(hb_local), "r"(r));

    asm volatile("barrier.cluster.arrive.aligned;" ::: "memory");
    asm volatile("barrier.cluster.wait.aligned;"   ::: "memory");

    float c_state = 0.0f;
    float gx_cur = valid ? __ldg(&Gx[grow]) : 0.0f;
    int ph[2] = {0, 0};

    for (int t = 0; t < F; t++) {
        const int pb = t & 1;
        float gx_next = (valid && (t + 1 < F))
                          ? __ldg(&Gx[(size_t)(t + 1) * 896 + grow]) : 0.0f;

        if (valid) {
            const ulonglong2* h4 =
                reinterpret_cast<const ulonglong2*>(&hbuf[pb][0]);
            unsigned long long a0 = 0ULL, a1 = 0ULL, a2 = 0ULL, a3 = 0ULL;
#pragma unroll
            for (int k = 0; k < 25; k++) {
                ulonglong2 hA = h4[2 * k];
                ulonglong2 hB = h4[2 * k + 1];
                fma2(a0, w[4 * k],     hA.x);
                fma2(a1, w[4 * k + 1], hA.y);
                fma2(a2, w[4 * k + 2], hB.x);
                fma2(a3, w[4 * k + 3], hB.y);
            }
            float l0, h0, l1, h1, l2, h2, l3, h3;
            unpack2(l0, h0, a0); unpack2(l1, h1, a1);
            unpack2(l2, h2, a2); unpack2(l3, h3, a3);
            sgate[tid] = ((l0 + h0) + (l1 + h1)) + ((l2 + h2) + (l3 + h3))
                         + gx_cur;
        }
        gx_cur = gx_next;
        __syncthreads();

        if (tid < 25) {
            float gi = sgate[tid];
            float gf = sgate[25 + tid];
            float gg = sgate[50 + tid];
            float go = sgate[75 + tid];
            float cn = siga(gf) * c_state + siga(gi) * tanha(gg);
            float hn = siga(go) * tanha(cn);
            c_state = cn;
            size_t cidx = (size_t)t * 712 + 25 * rank + tid;
            bf16 hh = __float2bfloat16(hn);
            CatH[cidx] = hh;
            CatL[cidx] = __float2bfloat16(hn - __bfloat162float(hh));
            uint32_t off = (uint32_t)((((t + 1) & 1) * 200 + 25 * rank + tid) * 4);
#pragma unroll
            for (int r = 0; r < 8; r++)
                asm volatile("st.shared::cluster.f32 [%0], %1;"
                             :: "r"(peer_h[r] + off), "f"(hn) : "memory");
        }

        __syncthreads();   // drains DSMEM STS before the signal

        if (tid == 0) {
#pragma unroll
            for (int r = 0; r < 8; r++) {
                uint32_t ba = peer_h[r] + bar_delta + (uint32_t)(pb * 8);
                asm volatile("mbarrier.arrive.shared::cluster.b64 _, [%0];"
                             :: "r"(ba) : "memory");
            }
        }
        mbar_wait(s2u(&bars[pb]), (uint32_t)ph[pb]);
        ph[pb] ^= 1;
    }

    asm volatile("barrier.cluster.arrive.aligned;" ::: "memory");
    asm volatile("barrier.cluster.wait.aligned;"   ::: "memory");
}

// ---------------------------------------------------------------------------
// launch
// ---------------------------------------------------------------------------
extern "C" void kernel_launch(void* const* d_in, const int* in_sizes, int n_in,
                              void* d_out, int out_size)
{
    const float* mag = (const float*)d_in[0];
    const float* W1  = (const float*)d_in[1];
    const float* b1  = (const float*)d_in[2];
    const float* W2  = (const float*)d_in[3];
    const float* b2  = (const float*)d_in[4];
    const float* W3  = (const float*)d_in[5];
    const float* b3  = (const float*)d_in[6];
    const float* W4  = (const float*)d_in[7];
    const float* b4  = (const float*)d_in[8];
    const float* Wf1 = (const float*)d_in[9];
    const float* bf1 = (const float*)d_in[10];
    const float* Wf2 = (const float*)d_in[11];
    const float* bf2 = (const float*)d_in[12];
    const float* Wih = (const float*)d_in[13];
    const float* bih = (const float*)d_in[14];
    const float* Whh = (const float*)d_in[15];
    const float* bhh = (const float*)d_in[16];

    const int F = in_sizes[0] / 2049;
    float* out = (float*)d_out;

    bf16 *Xh, *Xl, *W1h, *W1l, *W2h, *W2l, *Wihh, *Wihl, *Wf1h, *Wf1l;
    bf16 *Wf2h, *Wf2l, *W3h, *W3l, *W4h, *W4l;
    bf16 *E1h, *E1l, *Cath, *Catl, *T1h, *T1l, *T2h, *T2l, *Dh, *Dl;
    float *Gx, *bsum;
    cudaGetSymbolAddress((void**)&Xh, g_Xh);     cudaGetSymbolAddress((void**)&Xl, g_Xl);
    cudaGetSymbolAddress((void**)&W1h, g_W1h);   cudaGetSymbolAddress((void**)&W1l, g_W1l);
    cudaGetSymbolAddress((void**)&W2h, g_W2h);   cudaGetSymbolAddress((void**)&W2l, g_W2l);
    cudaGetSymbolAddress((void**)&Wihh, g_Wih_h);cudaGetSymbolAddress((void**)&Wihl, g_Wih_l);
    cudaGetSymbolAddress((void**)&Wf1h, g_Wf1h); cudaGetSymbolAddress((void**)&Wf1l, g_Wf1l);
    cudaGetSymbolAddress((void**)&Wf2h, g_Wf2h); cudaGetSymbolAddress((void**)&Wf2l, g_Wf2l);
    cudaGetSymbolAddress((void**)&W3h, g_W3h);   cudaGetSymbolAddress((void**)&W3l, g_W3l);
    cudaGetSymbolAddress((void**)&W4h, g_W4h);   cudaGetSymbolAddress((void**)&W4l, g_W4l);
    cudaGetSymbolAddress((void**)&E1h, g_E1h);   cudaGetSymbolAddress((void**)&E1l, g_E1l);
    cudaGetSymbolAddress((void**)&Cath, g_Cath); cudaGetSymbolAddress((void**)&Catl, g_Catl);
    cudaGetSymbolAddress((void**)&T1h, g_T1h);   cudaGetSymbolAddress((void**)&T1l, g_T1l);
    cudaGetSymbolAddress((void**)&T2h, g_T2h);   cudaGetSymbolAddress((void**)&T2l, g_T2l);
    cudaGetSymbolAddress((void**)&Dh, g_Dh);     cudaGetSymbolAddress((void**)&Dl, g_Dl);
    cudaGetSymbolAddress((void**)&Gx, g_Gx);
    cudaGetSymbolAddress((void**)&bsum, g_bsum);

    const int SM = 4 * 128 * 72 * 2;   // 73728 B
    cudaFuncSetAttribute(mma_gemm<0>, cudaFuncAttributeMaxDynamicSharedMemorySize, SM);
    cudaFuncSetAttribute(mma_gemm<1>, cudaFuncAttributeMaxDynamicSharedMemorySize, SM);
    cudaFuncSetAttribute(mma_gemm<2>, cudaFuncAttributeMaxDynamicSharedMemorySize, SM);

    // ---- prep ----
    bias_sum_kernel<<<4, 256>>>(bih, bhh, bsum, 800);
    transpose_split_mag<<<dim3(F / 32, 66), dim3(32, 8)>>>(mag, Xh, Xl, F);
    auto swl = [&](const float* W, int M, int K, bf16* Wh_, bf16* Wl_, int Mp, int Kp) {
        split_weight<<<(Mp * Kp + 255) / 256, 256>>>(W, M, K, Wh_, Wl_, Mp, Kp);
    };
    swl(W1, 1000, 2049, W1h, W1l, 1024, 2112);
    swl(W2,  400, 1000, W2h, W2l,  512, 1024);
    swl(Wih, 800,  400, Wihh, Wihl, 896, 512);
    swl(Wf1, 800,  600, Wf1h, Wf1l, 896, 640);
    swl(Wf2, 400,  800, Wf2h, Wf2l, 512, 896);
    swl(W3, 1000,  400, W3h, W3l, 1024, 512);
    swl(W4, 2049, 1000, W4h, W4l, 2176, 1024);

    const int FT = F / 128;
    // ---- phase 1 ----
    mma_gemm<0><<<dim3(FT, 8), 256, SM>>>(Xh, Xl, 2112, W1h, W1l, 2112,
        b1, 1000, E1h, E1l, nullptr, 1024, 0, nullptr, nullptr, F);
    mma_gemm<0><<<dim3(FT, 4), 256, SM>>>(E1h, E1l, 1024, W2h, W2l, 1024,
        b2, 400, Cath, Catl, nullptr, 712, 200, nullptr, nullptr, F);
    mma_gemm<1><<<dim3(FT, 7), 256, SM>>>(Cath + 200, Catl + 200, 712,
        Wihh, Wihl, 512, bsum, 800, nullptr, nullptr, Gx, 896, 0,
        nullptr, nullptr, F);

    // ---- scan ----
    lstm_scan_kernel<<<8, 128>>>(Whh, Gx, Cath, Catl, F);

    // ---- phase 2 ----
    mma_gemm<0><<<dim3(FT, 7), 256, SM>>>(Cath, Catl, 712, Wf1h, Wf1l, 640,
        bf1, 800, T1h, T1l, nullptr, 896, 0, nullptr, nullptr, F);
    mma_gemm<0><<<dim3(FT, 4), 256, SM>>>(T1h, T1l, 896, Wf2h, Wf2l, 896,
        bf2, 400, T2h, T2l, nullptr, 512, 0, nullptr, nullptr, F);
    mma_gemm<0><<<dim3(FT, 8), 256, SM>>>(T2h, T2l, 512, W3h, W3l, 512,
        b3, 1000, Dh, Dl, nullptr, 1024, 0, nullptr, nullptr, F);
    mma_gemm<2><<<dim3(FT, 17), 256, SM>>>(Dh, Dl, 1024, W4h, W4l, 1024,
        b4, 2049, nullptr, nullptr, nullptr, 0, 0, mag, out, F);
}